// round 2
// baseline (speedup 1.0000x reference)
#include <cuda_runtime.h>
#include <cstdint>
#include <math.h>

#define NN 100000
#define DD 128
#define DOUT 8

// ---------------- scratch (static device globals; no allocation) ----------------
__device__ float g_y[NN * DD];
__device__ float g_z[NN * DD];
__device__ float g_s[NN * DD];
__device__ float g_h1[NN * DD];
__device__ float g_h2[NN * DD];
__device__ float g_inv[NN];
__device__ float g_cnt[NN];
__device__ float g_y2[NN * DOUT];
__device__ float g_z2[NN * DOUT];

// ---------------- helpers ----------------
__device__ __forceinline__ void red_add_v4(float4* p, float4 v) {
    asm volatile("red.global.add.v4.f32 [%0], {%1,%2,%3,%4};"
                 :: "l"(p), "f"(v.x), "f"(v.y), "f"(v.z), "f"(v.w) : "memory");
}

// ---------------- degree count / reciprocal ----------------
__global__ void count_kernel(const int* __restrict__ ei, int E, float* __restrict__ cnt) {
    int i = blockIdx.x * blockDim.x + threadIdx.x;
    if (i < E) atomicAdd(&cnt[ei[E + i]], 1.0f);
}

__global__ void inv_kernel(const float* __restrict__ cnt, float* __restrict__ inv) {
    int i = blockIdx.x * blockDim.x + threadIdx.x;
    if (i < NN) inv[i] = 1.0f / fmaxf(cnt[i], 1.0f);
}

// ---------------- dual GEMM: Y = H @ Wl^T ; Z = H @ Wr^T + bl ----------------
// H: [nrows,128], Wl/Wr: [128,128] row-major ([o][k]), block tile 64 rows x 128 cols.
// SMEM: Wl^T, Wr^T as [k*132+o] (padded), A as [k*68+r] (padded).
#define SWL_STRIDE 132
#define SA_STRIDE  68
#define GEMM_SMEM_FLOATS (2 * 128 * SWL_STRIDE + 128 * SA_STRIDE)
#define GEMM_SMEM_BYTES  (GEMM_SMEM_FLOATS * 4)

__global__ __launch_bounds__(256) void gemm_dual(
    const float* __restrict__ H, const float* __restrict__ Wl,
    const float* __restrict__ Wr, const float* __restrict__ bl,
    float* __restrict__ Y, float* __restrict__ Z, int nrows)
{
    extern __shared__ float sm[];
    float* sWl = sm;                        // [k*132 + o]
    float* sWr = sm + 128 * SWL_STRIDE;     // [k*132 + o]
    float* sA  = sm + 2 * 128 * SWL_STRIDE; // [k*68 + r]

    const int tid = threadIdx.x;

    // Load both weight matrices transposed into SMEM (coalesced global reads).
    #pragma unroll
    for (int j = 0; j < 64; j++) {
        int idx = tid + 256 * j;       // 16384 elems
        int k = idx & 127, o = idx >> 7;
        sWl[k * SWL_STRIDE + o] = Wl[o * 128 + k];
        sWr[k * SWL_STRIDE + o] = Wr[o * 128 + k];
    }

    const int row0 = blockIdx.x * 64;
    #pragma unroll
    for (int j = 0; j < 32; j++) {
        int idx = tid + 256 * j;       // 8192 elems
        int r = idx >> 7, k = idx & 127;
        int row = row0 + r;
        sA[k * SA_STRIDE + r] = (row < nrows) ? H[(long long)row * 128 + k] : 0.0f;
    }
    __syncthreads();

    const int tx = tid & 15;   // col group: o = tx*8 .. tx*8+7
    const int ty = tid >> 4;   // row group: r = ty*4 .. ty*4+3

    float accY[4][8], accZ[4][8];
    #pragma unroll
    for (int j = 0; j < 4; j++)
        #pragma unroll
        for (int c = 0; c < 8; c++) { accY[j][c] = 0.0f; accZ[j][c] = 0.0f; }

    #pragma unroll 4
    for (int k = 0; k < 128; k++) {
        float4 a  = *(const float4*)&sA[k * SA_STRIDE + ty * 4];
        float4 l0 = *(const float4*)&sWl[k * SWL_STRIDE + tx * 8];
        float4 l1 = *(const float4*)&sWl[k * SWL_STRIDE + tx * 8 + 4];
        float4 r0 = *(const float4*)&sWr[k * SWL_STRIDE + tx * 8];
        float4 r1 = *(const float4*)&sWr[k * SWL_STRIDE + tx * 8 + 4];
        float av[4] = {a.x, a.y, a.z, a.w};
        float wl[8] = {l0.x, l0.y, l0.z, l0.w, l1.x, l1.y, l1.z, l1.w};
        float wr[8] = {r0.x, r0.y, r0.z, r0.w, r1.x, r1.y, r1.z, r1.w};
        #pragma unroll
        for (int j = 0; j < 4; j++)
            #pragma unroll
            for (int c = 0; c < 8; c++) {
                accY[j][c] = fmaf(av[j], wl[c], accY[j][c]);
                accZ[j][c] = fmaf(av[j], wr[c], accZ[j][c]);
            }
    }

    float bias[8];
    #pragma unroll
    for (int c = 0; c < 8; c++) bias[c] = __ldg(&bl[tx * 8 + c]);

    #pragma unroll
    for (int j = 0; j < 4; j++) {
        int row = row0 + ty * 4 + j;
        if (row < nrows) {
            long long base = (long long)row * 128 + tx * 8;
            float4 y0 = {accY[j][0], accY[j][1], accY[j][2], accY[j][3]};
            float4 y1 = {accY[j][4], accY[j][5], accY[j][6], accY[j][7]};
            float4 z0 = {accZ[j][0] + bias[0], accZ[j][1] + bias[1],
                         accZ[j][2] + bias[2], accZ[j][3] + bias[3]};
            float4 z1 = {accZ[j][4] + bias[4], accZ[j][5] + bias[5],
                         accZ[j][6] + bias[6], accZ[j][7] + bias[7]};
            *(float4*)&Y[base]     = y0;
            *(float4*)&Y[base + 4] = y1;
            *(float4*)&Z[base]     = z0;
            *(float4*)&Z[base + 4] = z1;
        }
    }
}

// ---------------- small GEMM for layer 2: Y2 = H@Wl2^T, Z2 = H@Wr2^T + bl2 ----------------
__global__ __launch_bounds__(256) void gemm_small(
    const float* __restrict__ H, const float* __restrict__ Wl,
    const float* __restrict__ Wr, const float* __restrict__ bl,
    float* __restrict__ Y, float* __restrict__ Z)
{
    __shared__ float sW[128 * 16];   // [k*16 + o], o<8 -> Wl rows, o>=8 -> Wr rows
    __shared__ float sH[16 * 128];

    const int tid = threadIdx.x;
    #pragma unroll
    for (int j = 0; j < 8; j++) {
        int idx = tid + 256 * j;     // 2048
        int o = idx & 15, k = idx >> 4;
        sW[k * 16 + o] = (o < 8) ? Wl[o * 128 + k] : Wr[(o - 8) * 128 + k];
    }
    const int row0 = blockIdx.x * 16;
    #pragma unroll
    for (int j = 0; j < 8; j++) {
        int idx = tid + 256 * j;     // 2048
        int r = idx >> 7, k = idx & 127;
        int row = row0 + r;
        sH[r * 128 + k] = (row < NN) ? H[(long long)row * 128 + k] : 0.0f;
    }
    __syncthreads();

    const int o = tid & 15, rl = tid >> 4;
    float acc = 0.0f;
    #pragma unroll 8
    for (int k = 0; k < 128; k++)
        acc = fmaf(sH[rl * 128 + k], sW[k * 16 + o], acc);

    int row = row0 + rl;
    if (row < NN) {
        if (o < 8) Y[row * 8 + o] = acc;
        else       Z[row * 8 + (o - 8)] = acc + __ldg(&bl[o - 8]);
    }
}

// ---------------- edge scatter: S[dst] += Y[src], d=128 (one warp per edge) ----------------
__global__ void scatter128(const int* __restrict__ ei, const float* __restrict__ Y,
                           float* __restrict__ S, int E)
{
    long long t = (long long)blockIdx.x * blockDim.x + threadIdx.x;
    int e = (int)(t >> 5);
    if (e >= E) return;
    int lane = (int)(t & 31);
    int src = ei[e];
    int dst = ei[E + e];
    float4 v = __ldg((const float4*)Y + src * 32 + lane);
    red_add_v4((float4*)S + dst * 32 + lane, v);
}

// ---------------- edge scatter for d=8 (two float4 per edge) ----------------
__global__ void scatter8(const int* __restrict__ ei, const float* __restrict__ Y,
                         float* __restrict__ S, int E)
{
    int t = blockIdx.x * blockDim.x + threadIdx.x;
    if (t >= 2 * E) return;
    int e = t >> 1, hf = t & 1;
    int src = ei[e];
    int dst = ei[E + e];
    float4 v = __ldg((const float4*)Y + src * 2 + hf);
    red_add_v4((float4*)S + dst * 2 + hf, v);
}

// ---------------- finalize: H' = [relu](S*inv + Z), d=128 ----------------
template <bool RELU>
__global__ void fin128(const float* __restrict__ S, const float* __restrict__ Z,
                       const float* __restrict__ inv, float* __restrict__ H)
{
    int idx = blockIdx.x * blockDim.x + threadIdx.x;  // float4 index
    if (idx >= NN * 32) return;
    int row = idx >> 5;
    float iv = inv[row];
    float4 s = ((const float4*)S)[idx];
    float4 z = ((const float4*)Z)[idx];
    float4 v;
    v.x = fmaf(s.x, iv, z.x); v.y = fmaf(s.y, iv, z.y);
    v.z = fmaf(s.z, iv, z.z); v.w = fmaf(s.w, iv, z.w);
    if (RELU) {
        v.x = fmaxf(v.x, 0.0f); v.y = fmaxf(v.y, 0.0f);
        v.z = fmaxf(v.z, 0.0f); v.w = fmaxf(v.w, 0.0f);
    }
    ((float4*)H)[idx] = v;
}

// ---------------- finalize layer 2 + log_softmax ----------------
__global__ void final2(const float* __restrict__ S, const float* __restrict__ Z,
                       const float* __restrict__ inv, float* __restrict__ outh,
                       float* __restrict__ outls)
{
    int row = blockIdx.x * blockDim.x + threadIdx.x;
    if (row >= NN) return;
    float iv = inv[row];
    float4 s0 = ((const float4*)S)[row * 2];
    float4 s1 = ((const float4*)S)[row * 2 + 1];
    float4 z0 = ((const float4*)Z)[row * 2];
    float4 z1 = ((const float4*)Z)[row * 2 + 1];
    float h[8];
    h[0] = fmaf(s0.x, iv, z0.x); h[1] = fmaf(s0.y, iv, z0.y);
    h[2] = fmaf(s0.z, iv, z0.z); h[3] = fmaf(s0.w, iv, z0.w);
    h[4] = fmaf(s1.x, iv, z1.x); h[5] = fmaf(s1.y, iv, z1.y);
    h[6] = fmaf(s1.z, iv, z1.z); h[7] = fmaf(s1.w, iv, z1.w);

    float4 o0 = {h[0], h[1], h[2], h[3]};
    float4 o1 = {h[4], h[5], h[6], h[7]};
    ((float4*)outh)[row * 2]     = o0;
    ((float4*)outh)[row * 2 + 1] = o1;

    if (outls) {
        float m = h[0];
        #pragma unroll
        for (int j = 1; j < 8; j++) m = fmaxf(m, h[j]);
        float sum = 0.0f;
        #pragma unroll
        for (int j = 0; j < 8; j++) sum += expf(h[j] - m);
        float lse = logf(sum) + m;
        float4 l0 = {h[0] - lse, h[1] - lse, h[2] - lse, h[3] - lse};
        float4 l1 = {h[4] - lse, h[5] - lse, h[6] - lse, h[7] - lse};
        ((float4*)outls)[row * 2]     = l0;
        ((float4*)outls)[row * 2 + 1] = l1;
    }
}

// ---------------- launch ----------------
extern "C" void kernel_launch(void* const* d_in, const int* in_sizes, int n_in,
                              void* d_out, int out_size)
{
    const float* x   = (const float*)d_in[0];
    const int*   ei  = (const int*)d_in[1];   // int32: JAX default config downcasts int64
    const float* Wl0 = (const float*)d_in[2];
    const float* bl0 = (const float*)d_in[3];
    const float* Wr0 = (const float*)d_in[4];
    const float* Wl1 = (const float*)d_in[5];
    const float* bl1 = (const float*)d_in[6];
    const float* Wr1 = (const float*)d_in[7];
    const float* Wl2 = (const float*)d_in[8];
    const float* bl2 = (const float*)d_in[9];
    const float* Wr2 = (const float*)d_in[10];
    const int E = in_sizes[1] / 2;
    float* out = (float*)d_out;

    void *py, *pz, *ps, *ph1, *ph2, *pinv, *pcnt, *py2, *pz2;
    cudaGetSymbolAddress(&py,  g_y);
    cudaGetSymbolAddress(&pz,  g_z);
    cudaGetSymbolAddress(&ps,  g_s);
    cudaGetSymbolAddress(&ph1, g_h1);
    cudaGetSymbolAddress(&ph2, g_h2);
    cudaGetSymbolAddress(&pinv, g_inv);
    cudaGetSymbolAddress(&pcnt, g_cnt);
    cudaGetSymbolAddress(&py2, g_y2);
    cudaGetSymbolAddress(&pz2, g_z2);

    cudaFuncSetAttribute(gemm_dual, cudaFuncAttributeMaxDynamicSharedMemorySize, GEMM_SMEM_BYTES);

    const int tiles = (NN + 63) / 64;
    const int scat_blocks = (int)(((long long)E * 32 + 255) / 256);
    const int fin_blocks  = (NN * 32 + 255) / 256;

    // degrees
    cudaMemsetAsync(pcnt, 0, NN * sizeof(float));
    count_kernel<<<(E + 255) / 256, 256>>>(ei, E, (float*)pcnt);
    inv_kernel<<<(NN + 255) / 256, 256>>>((const float*)pcnt, (float*)pinv);

    // ---- layer 0: x -> h1 ----
    gemm_dual<<<tiles, 256, GEMM_SMEM_BYTES>>>(x, Wl0, Wr0, bl0, (float*)py, (float*)pz, NN);
    cudaMemsetAsync(ps, 0, (size_t)NN * DD * sizeof(float));
    scatter128<<<scat_blocks, 256>>>(ei, (const float*)py, (float*)ps, E);
    fin128<true><<<fin_blocks, 256>>>((const float*)ps, (const float*)pz, (const float*)pinv, (float*)ph1);

    // ---- layer 1: h1 -> h2 ----
    gemm_dual<<<tiles, 256, GEMM_SMEM_BYTES>>>((const float*)ph1, Wl1, Wr1, bl1, (float*)py, (float*)pz, NN);
    cudaMemsetAsync(ps, 0, (size_t)NN * DD * sizeof(float));
    scatter128<<<scat_blocks, 256>>>(ei, (const float*)py, (float*)ps, E);
    fin128<true><<<fin_blocks, 256>>>((const float*)ps, (const float*)pz, (const float*)pinv, (float*)ph2);

    // ---- layer 2: h2 -> out (h3, log_softmax) ----
    gemm_small<<<(NN + 15) / 16, 256>>>((const float*)ph2, Wl2, Wr2, bl2, (float*)py2, (float*)pz2);
    cudaMemsetAsync(ps, 0, (size_t)NN * DOUT * sizeof(float));
    scatter8<<<(2 * E + 255) / 256, 256>>>(ei, (const float*)py2, (float*)ps, E);

    float* outls = (out_size >= 2 * NN * DOUT) ? (out + (size_t)NN * DOUT) : nullptr;
    final2<<<(NN + 255) / 256, 256>>>((const float*)ps, (const float*)pz2, (const float*)pinv, out, outls);
}

// round 3
// speedup vs baseline: 1.3965x; 1.3965x over previous
#include <cuda_runtime.h>
#include <cstdint>
#include <math.h>

#define NN 100000
#define DD 128
#define DOUT 8
#define EMAX 1600000
#define SCAN_BS 512
#define SCAN_NB ((NN + SCAN_BS - 1) / SCAN_BS)   // 196

// ---------------- scratch (static device globals; no allocation) ----------------
__device__ float g_y[NN * DD];
__device__ float g_z[NN * DD];
__device__ float g_h1[NN * DD];
__device__ float g_h2[NN * DD];
__device__ float g_y2[NN * DOUT];
__device__ float g_z2[NN * DOUT];
__device__ int   g_cnt[NN];
__device__ int   g_offs[NN + 1];
__device__ int   g_cursor[NN];
__device__ int   g_bsum[SCAN_NB];
__device__ int   g_csr[EMAX];

// ================= CSR build =================
__global__ void hist_kernel(const int* __restrict__ ei, int E, int* __restrict__ cnt) {
    int i = blockIdx.x * blockDim.x + threadIdx.x;
    if (i < E) atomicAdd(&cnt[ei[E + i]], 1);
}

__global__ void scan_block(const int* __restrict__ cnt, int* __restrict__ offs,
                           int* __restrict__ bsum) {
    __shared__ int sm[SCAN_BS];
    int i = blockIdx.x * SCAN_BS + threadIdx.x;
    int v = (i < NN) ? cnt[i] : 0;
    sm[threadIdx.x] = v;
    __syncthreads();
    // Hillis-Steele inclusive scan
    #pragma unroll
    for (int d = 1; d < SCAN_BS; d <<= 1) {
        int t = (threadIdx.x >= d) ? sm[threadIdx.x - d] : 0;
        __syncthreads();
        sm[threadIdx.x] += t;
        __syncthreads();
    }
    if (i < NN) offs[i] = sm[threadIdx.x] - v;   // exclusive
    if (threadIdx.x == SCAN_BS - 1) bsum[blockIdx.x] = sm[threadIdx.x];
}

__global__ void scan_top(int* __restrict__ bsum) {
    __shared__ int sm[256];
    int i = threadIdx.x;
    int v = (i < SCAN_NB) ? bsum[i] : 0;
    sm[i] = v;
    __syncthreads();
    #pragma unroll
    for (int d = 1; d < 256; d <<= 1) {
        int t = (i >= d) ? sm[i - d] : 0;
        __syncthreads();
        sm[i] += t;
        __syncthreads();
    }
    if (i < SCAN_NB) bsum[i] = sm[i] - v;        // exclusive
}

__global__ void scan_add(int* __restrict__ offs, const int* __restrict__ bsum,
                         int* __restrict__ cursor, int E) {
    int i = blockIdx.x * blockDim.x + threadIdx.x;
    if (i < NN) {
        int v = offs[i] + bsum[i / SCAN_BS];
        offs[i] = v;
        cursor[i] = v;
    }
    if (i == 0) offs[NN] = E;
}

__global__ void fill_kernel(const int* __restrict__ ei, int E,
                            int* __restrict__ cursor, int* __restrict__ csr) {
    int e = blockIdx.x * blockDim.x + threadIdx.x;
    if (e < E) {
        int pos = atomicAdd(&cursor[ei[E + e]], 1);
        csr[pos] = ei[e];
    }
}

// ---------------- dual GEMM: Y = H @ Wl^T ; Z = H @ Wr^T + bl ----------------
#define SWL_STRIDE 132
#define SA_STRIDE  68
#define GEMM_SMEM_FLOATS (2 * 128 * SWL_STRIDE + 128 * SA_STRIDE)
#define GEMM_SMEM_BYTES  (GEMM_SMEM_FLOATS * 4)

__global__ __launch_bounds__(256) void gemm_dual(
    const float* __restrict__ H, const float* __restrict__ Wl,
    const float* __restrict__ Wr, const float* __restrict__ bl,
    float* __restrict__ Y, float* __restrict__ Z, int nrows)
{
    extern __shared__ float sm[];
    float* sWl = sm;
    float* sWr = sm + 128 * SWL_STRIDE;
    float* sA  = sm + 2 * 128 * SWL_STRIDE;

    const int tid = threadIdx.x;

    #pragma unroll
    for (int j = 0; j < 64; j++) {
        int idx = tid + 256 * j;
        int k = idx & 127, o = idx >> 7;
        sWl[k * SWL_STRIDE + o] = Wl[o * 128 + k];
        sWr[k * SWL_STRIDE + o] = Wr[o * 128 + k];
    }

    const int row0 = blockIdx.x * 64;
    #pragma unroll
    for (int j = 0; j < 32; j++) {
        int idx = tid + 256 * j;
        int r = idx >> 7, k = idx & 127;
        int row = row0 + r;
        sA[k * SA_STRIDE + r] = (row < nrows) ? H[(long long)row * 128 + k] : 0.0f;
    }
    __syncthreads();

    const int tx = tid & 15;
    const int ty = tid >> 4;

    float accY[4][8], accZ[4][8];
    #pragma unroll
    for (int j = 0; j < 4; j++)
        #pragma unroll
        for (int c = 0; c < 8; c++) { accY[j][c] = 0.0f; accZ[j][c] = 0.0f; }

    #pragma unroll 4
    for (int k = 0; k < 128; k++) {
        float4 a  = *(const float4*)&sA[k * SA_STRIDE + ty * 4];
        float4 l0 = *(const float4*)&sWl[k * SWL_STRIDE + tx * 8];
        float4 l1 = *(const float4*)&sWl[k * SWL_STRIDE + tx * 8 + 4];
        float4 r0 = *(const float4*)&sWr[k * SWL_STRIDE + tx * 8];
        float4 r1 = *(const float4*)&sWr[k * SWL_STRIDE + tx * 8 + 4];
        float av[4] = {a.x, a.y, a.z, a.w};
        float wl[8] = {l0.x, l0.y, l0.z, l0.w, l1.x, l1.y, l1.z, l1.w};
        float wr[8] = {r0.x, r0.y, r0.z, r0.w, r1.x, r1.y, r1.z, r1.w};
        #pragma unroll
        for (int j = 0; j < 4; j++)
            #pragma unroll
            for (int c = 0; c < 8; c++) {
                accY[j][c] = fmaf(av[j], wl[c], accY[j][c]);
                accZ[j][c] = fmaf(av[j], wr[c], accZ[j][c]);
            }
    }

    float bias[8];
    #pragma unroll
    for (int c = 0; c < 8; c++) bias[c] = __ldg(&bl[tx * 8 + c]);

    #pragma unroll
    for (int j = 0; j < 4; j++) {
        int row = row0 + ty * 4 + j;
        if (row < nrows) {
            long long base = (long long)row * 128 + tx * 8;
            float4 y0 = {accY[j][0], accY[j][1], accY[j][2], accY[j][3]};
            float4 y1 = {accY[j][4], accY[j][5], accY[j][6], accY[j][7]};
            float4 z0 = {accZ[j][0] + bias[0], accZ[j][1] + bias[1],
                         accZ[j][2] + bias[2], accZ[j][3] + bias[3]};
            float4 z1 = {accZ[j][4] + bias[4], accZ[j][5] + bias[5],
                         accZ[j][6] + bias[6], accZ[j][7] + bias[7]};
            *(float4*)&Y[base]     = y0;
            *(float4*)&Y[base + 4] = y1;
            *(float4*)&Z[base]     = z0;
            *(float4*)&Z[base + 4] = z1;
        }
    }
}

// ---------------- small GEMM for layer 2 ----------------
__global__ __launch_bounds__(256) void gemm_small(
    const float* __restrict__ H, const float* __restrict__ Wl,
    const float* __restrict__ Wr, const float* __restrict__ bl,
    float* __restrict__ Y, float* __restrict__ Z)
{
    __shared__ float sW[128 * 16];
    __shared__ float sH[16 * 128];

    const int tid = threadIdx.x;
    #pragma unroll
    for (int j = 0; j < 8; j++) {
        int idx = tid + 256 * j;
        int o = idx & 15, k = idx >> 4;
        sW[k * 16 + o] = (o < 8) ? Wl[o * 128 + k] : Wr[(o - 8) * 128 + k];
    }
    const int row0 = blockIdx.x * 16;
    #pragma unroll
    for (int j = 0; j < 8; j++) {
        int idx = tid + 256 * j;
        int r = idx >> 7, k = idx & 127;
        int row = row0 + r;
        sH[r * 128 + k] = (row < NN) ? H[(long long)row * 128 + k] : 0.0f;
    }
    __syncthreads();

    const int o = tid & 15, rl = tid >> 4;
    float acc = 0.0f;
    #pragma unroll 8
    for (int k = 0; k < 128; k++)
        acc = fmaf(sH[rl * 128 + k], sW[k * 16 + o], acc);

    int row = row0 + rl;
    if (row < NN) {
        if (o < 8) Y[row * 8 + o] = acc;
        else       Z[row * 8 + (o - 8)] = acc + __ldg(&bl[o - 8]);
    }
}

// ========== gather aggregate d=128: H = relu(mean_{src in N(dst)} Y[src] + Z[dst]) ==========
__global__ __launch_bounds__(256) void gather128(
    const int* __restrict__ csr, const int* __restrict__ offs,
    const float* __restrict__ Y, const float* __restrict__ Z,
    float* __restrict__ H)
{
    int node = blockIdx.x * 8 + (threadIdx.x >> 5);
    if (node >= NN) return;
    int lane = threadIdx.x & 31;
    int beg = offs[node], end = offs[node + 1];

    float4 acc = {0.0f, 0.0f, 0.0f, 0.0f};
    const float4* Y4 = (const float4*)Y;

    for (int j = beg; j < end; j += 32) {
        int chunk = min(32, end - j);
        int id = (lane < chunk) ? csr[j + lane] : 0;
        int t = 0;
        for (; t + 4 <= chunk; t += 4) {
            int s0 = __shfl_sync(0xffffffffu, id, t);
            int s1 = __shfl_sync(0xffffffffu, id, t + 1);
            int s2 = __shfl_sync(0xffffffffu, id, t + 2);
            int s3 = __shfl_sync(0xffffffffu, id, t + 3);
            float4 v0 = __ldg(Y4 + s0 * 32 + lane);
            float4 v1 = __ldg(Y4 + s1 * 32 + lane);
            float4 v2 = __ldg(Y4 + s2 * 32 + lane);
            float4 v3 = __ldg(Y4 + s3 * 32 + lane);
            acc.x += v0.x + v1.x + v2.x + v3.x;
            acc.y += v0.y + v1.y + v2.y + v3.y;
            acc.z += v0.z + v1.z + v2.z + v3.z;
            acc.w += v0.w + v1.w + v2.w + v3.w;
        }
        for (; t < chunk; t++) {
            int s = __shfl_sync(0xffffffffu, id, t);
            float4 v = __ldg(Y4 + s * 32 + lane);
            acc.x += v.x; acc.y += v.y; acc.z += v.z; acc.w += v.w;
        }
    }

    float iv = 1.0f / (float)max(end - beg, 1);
    float4 z = __ldg((const float4*)Z + node * 32 + lane);
    float4 v;
    v.x = fmaxf(fmaf(acc.x, iv, z.x), 0.0f);
    v.y = fmaxf(fmaf(acc.y, iv, z.y), 0.0f);
    v.z = fmaxf(fmaf(acc.z, iv, z.z), 0.0f);
    v.w = fmaxf(fmaf(acc.w, iv, z.w), 0.0f);
    ((float4*)H)[node * 32 + lane] = v;
}

// ========== gather d=8 + finalize + log_softmax (4 lanes per node) ==========
__global__ __launch_bounds__(256) void gather8(
    const int* __restrict__ csr, const int* __restrict__ offs,
    const float* __restrict__ Y, const float* __restrict__ Z,
    float* __restrict__ outh, float* __restrict__ outls)
{
    int node = blockIdx.x * 64 + (threadIdx.x >> 2);
    if (node >= NN) return;
    int lane4 = threadIdx.x & 3;
    int beg = offs[node], end = offs[node + 1];

    float a[8] = {0, 0, 0, 0, 0, 0, 0, 0};
    const float4* Y4 = (const float4*)Y;
    for (int j = beg + lane4; j < end; j += 4) {
        int s = csr[j];
        float4 v0 = __ldg(Y4 + s * 2);
        float4 v1 = __ldg(Y4 + s * 2 + 1);
        a[0] += v0.x; a[1] += v0.y; a[2] += v0.z; a[3] += v0.w;
        a[4] += v1.x; a[5] += v1.y; a[6] += v1.z; a[7] += v1.w;
    }
    // reduce across the 4 lanes of the group (groups are warp-aligned)
    #pragma unroll
    for (int i = 0; i < 8; i++) {
        a[i] += __shfl_xor_sync(0xffffffffu, a[i], 1);
        a[i] += __shfl_xor_sync(0xffffffffu, a[i], 2);
    }
    if (lane4 != 0) return;

    float iv = 1.0f / (float)max(end - beg, 1);
    float4 z0 = __ldg((const float4*)Z + node * 2);
    float4 z1 = __ldg((const float4*)Z + node * 2 + 1);
    float h[8];
    h[0] = fmaf(a[0], iv, z0.x); h[1] = fmaf(a[1], iv, z0.y);
    h[2] = fmaf(a[2], iv, z0.z); h[3] = fmaf(a[3], iv, z0.w);
    h[4] = fmaf(a[4], iv, z1.x); h[5] = fmaf(a[5], iv, z1.y);
    h[6] = fmaf(a[6], iv, z1.z); h[7] = fmaf(a[7], iv, z1.w);

    ((float4*)outh)[node * 2]     = make_float4(h[0], h[1], h[2], h[3]);
    ((float4*)outh)[node * 2 + 1] = make_float4(h[4], h[5], h[6], h[7]);

    if (outls) {
        float m = h[0];
        #pragma unroll
        for (int j = 1; j < 8; j++) m = fmaxf(m, h[j]);
        float sum = 0.0f;
        #pragma unroll
        for (int j = 0; j < 8; j++) sum += expf(h[j] - m);
        float lse = logf(sum) + m;
        ((float4*)outls)[node * 2]     = make_float4(h[0]-lse, h[1]-lse, h[2]-lse, h[3]-lse);
        ((float4*)outls)[node * 2 + 1] = make_float4(h[4]-lse, h[5]-lse, h[6]-lse, h[7]-lse);
    }
}

// ---------------- launch ----------------
extern "C" void kernel_launch(void* const* d_in, const int* in_sizes, int n_in,
                              void* d_out, int out_size)
{
    const float* x   = (const float*)d_in[0];
    const int*   ei  = (const int*)d_in[1];   // int32 (JAX default downcasts int64)
    const float* Wl0 = (const float*)d_in[2];
    const float* bl0 = (const float*)d_in[3];
    const float* Wr0 = (const float*)d_in[4];
    const float* Wl1 = (const float*)d_in[5];
    const float* bl1 = (const float*)d_in[6];
    const float* Wr1 = (const float*)d_in[7];
    const float* Wl2 = (const float*)d_in[8];
    const float* bl2 = (const float*)d_in[9];
    const float* Wr2 = (const float*)d_in[10];
    int E = in_sizes[1] / 2;
    if (E > EMAX) E = EMAX;
    float* out = (float*)d_out;

    void *py, *pz, *ph1, *ph2, *py2, *pz2, *pcnt, *poffs, *pcur, *pbsum, *pcsr;
    cudaGetSymbolAddress(&py,   g_y);
    cudaGetSymbolAddress(&pz,   g_z);
    cudaGetSymbolAddress(&ph1,  g_h1);
    cudaGetSymbolAddress(&ph2,  g_h2);
    cudaGetSymbolAddress(&py2,  g_y2);
    cudaGetSymbolAddress(&pz2,  g_z2);
    cudaGetSymbolAddress(&pcnt, g_cnt);
    cudaGetSymbolAddress(&poffs,g_offs);
    cudaGetSymbolAddress(&pcur, g_cursor);
    cudaGetSymbolAddress(&pbsum,g_bsum);
    cudaGetSymbolAddress(&pcsr, g_csr);

    cudaFuncSetAttribute(gemm_dual, cudaFuncAttributeMaxDynamicSharedMemorySize, GEMM_SMEM_BYTES);

    const int tiles = (NN + 63) / 64;

    // ---- build CSR (dst-major) ----
    cudaMemsetAsync(pcnt, 0, NN * sizeof(int));
    hist_kernel<<<(E + 255) / 256, 256>>>(ei, E, (int*)pcnt);
    scan_block<<<SCAN_NB, SCAN_BS>>>((const int*)pcnt, (int*)poffs, (int*)pbsum);
    scan_top<<<1, 256>>>((int*)pbsum);
    scan_add<<<(NN + 255) / 256, 256>>>((int*)poffs, (const int*)pbsum, (int*)pcur, E);
    fill_kernel<<<(E + 255) / 256, 256>>>(ei, E, (int*)pcur, (int*)pcsr);

    // ---- layer 0: x -> h1 ----
    gemm_dual<<<tiles, 256, GEMM_SMEM_BYTES>>>(x, Wl0, Wr0, bl0, (float*)py, (float*)pz, NN);
    gather128<<<(NN + 7) / 8, 256>>>((const int*)pcsr, (const int*)poffs,
                                     (const float*)py, (const float*)pz, (float*)ph1);

    // ---- layer 1: h1 -> h2 ----
    gemm_dual<<<tiles, 256, GEMM_SMEM_BYTES>>>((const float*)ph1, Wl1, Wr1, bl1,
                                               (float*)py, (float*)pz, NN);
    gather128<<<(NN + 7) / 8, 256>>>((const int*)pcsr, (const int*)poffs,
                                     (const float*)py, (const float*)pz, (float*)ph2);

    // ---- layer 2: h2 -> out ----
    gemm_small<<<(NN + 15) / 16, 256>>>((const float*)ph2, Wl2, Wr2, bl2,
                                        (float*)py2, (float*)pz2);
    float* outls = (out_size >= 2 * NN * DOUT) ? (out + (size_t)NN * DOUT) : nullptr;
    gather8<<<(NN + 63) / 64, 256>>>((const int*)pcsr, (const int*)poffs,
                                     (const float*)py2, (const float*)pz2, out, outls);
}

// round 4
// speedup vs baseline: 2.5594x; 1.8327x over previous
#include <cuda_runtime.h>
#include <cuda_bf16.h>
#include <cstdint>
#include <math.h>

#define NN 100000
#define DD 128
#define DOUT 8
#define EMAX 1600000
#define SCAN_BS 512
#define SCAN_NB ((NN + SCAN_BS - 1) / SCAN_BS)   // 196

// ---------------- scratch (static device globals; no allocation) ----------------
__device__ float g_y[NN * DD];
__device__ float g_z[NN * DD];
__device__ float g_h1[NN * DD];
__device__ float g_h2[NN * DD];
__device__ float g_y2[NN * DOUT];
__device__ float g_z2[NN * DOUT];
__device__ int   g_cnt[NN];
__device__ int   g_offs[NN + 1];
__device__ int   g_cursor[NN];
__device__ int   g_bsum[SCAN_NB];
__device__ int   g_csr[EMAX];

// ================= CSR build =================
__global__ void hist_kernel(const int* __restrict__ ei, int E, int* __restrict__ cnt) {
    int i = blockIdx.x * blockDim.x + threadIdx.x;
    if (i < E) atomicAdd(&cnt[ei[E + i]], 1);
}

__global__ void scan_block(const int* __restrict__ cnt, int* __restrict__ offs,
                           int* __restrict__ bsum) {
    __shared__ int sm[SCAN_BS];
    int i = blockIdx.x * SCAN_BS + threadIdx.x;
    int v = (i < NN) ? cnt[i] : 0;
    sm[threadIdx.x] = v;
    __syncthreads();
    #pragma unroll
    for (int d = 1; d < SCAN_BS; d <<= 1) {
        int t = (threadIdx.x >= d) ? sm[threadIdx.x - d] : 0;
        __syncthreads();
        sm[threadIdx.x] += t;
        __syncthreads();
    }
    if (i < NN) offs[i] = sm[threadIdx.x] - v;   // exclusive
    if (threadIdx.x == SCAN_BS - 1) bsum[blockIdx.x] = sm[threadIdx.x];
}

__global__ void scan_top(int* __restrict__ bsum) {
    __shared__ int sm[256];
    int i = threadIdx.x;
    int v = (i < SCAN_NB) ? bsum[i] : 0;
    sm[i] = v;
    __syncthreads();
    #pragma unroll
    for (int d = 1; d < 256; d <<= 1) {
        int t = (i >= d) ? sm[i - d] : 0;
        __syncthreads();
        sm[i] += t;
        __syncthreads();
    }
    if (i < SCAN_NB) bsum[i] = sm[i] - v;        // exclusive
}

__global__ void scan_add(int* __restrict__ offs, const int* __restrict__ bsum,
                         int* __restrict__ cursor, int E) {
    int i = blockIdx.x * blockDim.x + threadIdx.x;
    if (i < NN) {
        int v = offs[i] + bsum[i / SCAN_BS];
        offs[i] = v;
        cursor[i] = v;
    }
    if (i == 0) offs[NN] = E;
}

__global__ void fill_kernel(const int* __restrict__ ei, int E,
                            int* __restrict__ cursor, int* __restrict__ csr) {
    int e = blockIdx.x * blockDim.x + threadIdx.x;
    if (e < E) {
        int pos = atomicAdd(&cursor[ei[E + e]], 1);
        csr[pos] = ei[e];
    }
}

// ================ dual GEMM via bf16 tensor cores (split precision) ================
// C[64 x 256] = A[64 x 128] @ Wcat^T, Wcat = [Wl ; Wr] (256 x 128).
// a = ah + al (bf16 split); product = ah*bh + al*bh + ah*bl, fp32 accumulate.
#define AST 136
#define BST 136
#define SM_AH 0
#define SM_AL (64 * AST)
#define SM_BH (2 * 64 * AST)
#define SM_BL (2 * 64 * AST + 256 * BST)
#define MMA_SMEM_BF16 (2 * 64 * AST + 2 * 256 * BST)
#define MMA_SMEM_BYTES (MMA_SMEM_BF16 * 2)

__device__ __forceinline__ void mma_bf16(float& c0, float& c1, float& c2, float& c3,
                                         uint32_t a0, uint32_t a1, uint32_t a2, uint32_t a3,
                                         uint32_t b0, uint32_t b1) {
    asm volatile(
        "mma.sync.aligned.m16n8k16.row.col.f32.bf16.bf16.f32 "
        "{%0,%1,%2,%3}, {%4,%5,%6,%7}, {%8,%9}, {%0,%1,%2,%3};"
        : "+f"(c0), "+f"(c1), "+f"(c2), "+f"(c3)
        : "r"(a0), "r"(a1), "r"(a2), "r"(a3), "r"(b0), "r"(b1));
}

__global__ __launch_bounds__(256) void gemm_dual_mma(
    const float* __restrict__ H, const float* __restrict__ Wl,
    const float* __restrict__ Wr, const float* __restrict__ bl,
    float* __restrict__ Y, float* __restrict__ Z, int nrows)
{
    extern __shared__ __nv_bfloat16 sb[];
    __nv_bfloat16* sAh = sb + SM_AH;
    __nv_bfloat16* sAl = sb + SM_AL;
    __nv_bfloat16* sBh = sb + SM_BH;
    __nv_bfloat16* sBl = sb + SM_BL;

    const int tid = threadIdx.x;
    const int row0 = blockIdx.x * 64;

    // ---- weights -> smem bf16 hi/lo. Wcat[n][k]: n<128 -> Wl, else Wr. ----
    {
        const float4* Wl4 = (const float4*)Wl;
        const float4* Wr4 = (const float4*)Wr;
        #pragma unroll
        for (int j = 0; j < 32; j++) {
            int idx4 = tid + 256 * j;            // 8192 float4
            int n = idx4 >> 5, k4 = idx4 & 31;
            float4 w = (n < 128) ? __ldg(Wl4 + idx4) : __ldg(Wr4 + idx4 - 4096);
            float wv[4] = {w.x, w.y, w.z, w.w};
            int base = n * BST + k4 * 4;
            #pragma unroll
            for (int u = 0; u < 4; u++) {
                __nv_bfloat16 hi = __float2bfloat16(wv[u]);
                sBh[base + u] = hi;
                sBl[base + u] = __float2bfloat16(wv[u] - __bfloat162float(hi));
            }
        }
    }
    // ---- A tile -> smem bf16 hi/lo ----
    {
        const float4* H4 = (const float4*)H;
        #pragma unroll
        for (int j = 0; j < 8; j++) {
            int idx4 = tid + 256 * j;            // 2048 float4
            int r = idx4 >> 5, k4 = idx4 & 31;
            int row = row0 + r;
            float4 v = (row < nrows) ? __ldg(H4 + (long long)row * 32 + k4)
                                     : make_float4(0.f, 0.f, 0.f, 0.f);
            float av[4] = {v.x, v.y, v.z, v.w};
            int base = r * AST + k4 * 4;
            #pragma unroll
            for (int u = 0; u < 4; u++) {
                __nv_bfloat16 hi = __float2bfloat16(av[u]);
                sAh[base + u] = hi;
                sAl[base + u] = __float2bfloat16(av[u] - __bfloat162float(hi));
            }
        }
    }
    __syncthreads();

    const int lane = tid & 31, wid = tid >> 5;
    const int wm = wid & 3, wn = wid >> 2;       // 4 warps along M, 2 along N
    const int m_base = wm * 16, n_base = wn * 128;
    const int g = lane >> 2, c2 = (lane & 3) * 2;

    float acc[16][4];
    #pragma unroll
    for (int nt = 0; nt < 16; nt++)
        #pragma unroll
        for (int u = 0; u < 4; u++) acc[nt][u] = 0.0f;

    #pragma unroll
    for (int ks = 0; ks < 24; ks++) {
        const int seg = ks >> 3;
        const int k0 = (ks & 7) * 16;
        const __nv_bfloat16* As = (seg == 1) ? sAl : sAh;
        const __nv_bfloat16* Bs = (seg == 2) ? sBl : sBh;

        uint32_t a0 = *(const uint32_t*)&As[(m_base + g)     * AST + k0 + c2];
        uint32_t a1 = *(const uint32_t*)&As[(m_base + g + 8) * AST + k0 + c2];
        uint32_t a2 = *(const uint32_t*)&As[(m_base + g)     * AST + k0 + 8 + c2];
        uint32_t a3 = *(const uint32_t*)&As[(m_base + g + 8) * AST + k0 + 8 + c2];

        #pragma unroll
        for (int nt = 0; nt < 16; nt++) {
            const __nv_bfloat16* bp = &Bs[(n_base + nt * 8 + g) * BST + k0 + c2];
            uint32_t b0 = *(const uint32_t*)bp;
            uint32_t b1 = *(const uint32_t*)(bp + 8);
            mma_bf16(acc[nt][0], acc[nt][1], acc[nt][2], acc[nt][3],
                     a0, a1, a2, a3, b0, b1);
        }
    }

    // ---- epilogue: n<128 -> Y, n>=128 -> Z (+bias) ----
    const int row_a = row0 + m_base + g;
    const int row_b = row_a + 8;
    #pragma unroll
    for (int nt = 0; nt < 16; nt++) {
        int n = n_base + nt * 8 + c2;
        float b0v = 0.0f, b1v = 0.0f;
        float* O;
        int col;
        if (n < 128) { O = Y; col = n; }
        else { O = Z; col = n - 128; b0v = __ldg(&bl[col]); b1v = __ldg(&bl[col + 1]); }
        if (row_a < nrows) {
            float2 v = {acc[nt][0] + b0v, acc[nt][1] + b1v};
            *(float2*)&O[(long long)row_a * 128 + col] = v;
        }
        if (row_b < nrows) {
            float2 v = {acc[nt][2] + b0v, acc[nt][3] + b1v};
            *(float2*)&O[(long long)row_b * 128 + col] = v;
        }
    }
}

// ---------------- small GEMM for layer 2 ----------------
__global__ __launch_bounds__(256) void gemm_small(
    const float* __restrict__ H, const float* __restrict__ Wl,
    const float* __restrict__ Wr, const float* __restrict__ bl,
    float* __restrict__ Y, float* __restrict__ Z)
{
    __shared__ float sW[128 * 16];
    __shared__ float sH[16 * 128];

    const int tid = threadIdx.x;
    #pragma unroll
    for (int j = 0; j < 8; j++) {
        int idx = tid + 256 * j;
        int o = idx & 15, k = idx >> 4;
        sW[k * 16 + o] = (o < 8) ? Wl[o * 128 + k] : Wr[(o - 8) * 128 + k];
    }
    const int row0 = blockIdx.x * 16;
    #pragma unroll
    for (int j = 0; j < 8; j++) {
        int idx = tid + 256 * j;
        int r = idx >> 7, k = idx & 127;
        int row = row0 + r;
        sH[r * 128 + k] = (row < NN) ? H[(long long)row * 128 + k] : 0.0f;
    }
    __syncthreads();

    const int o = tid & 15, rl = tid >> 4;
    float acc = 0.0f;
    #pragma unroll 8
    for (int k = 0; k < 128; k++)
        acc = fmaf(sH[rl * 128 + k], sW[k * 16 + o], acc);

    int row = row0 + rl;
    if (row < NN) {
        if (o < 8) Y[row * 8 + o] = acc;
        else       Z[row * 8 + (o - 8)] = acc + __ldg(&bl[o - 8]);
    }
}

// ========== gather aggregate d=128 ==========
__global__ __launch_bounds__(256) void gather128(
    const int* __restrict__ csr, const int* __restrict__ offs,
    const float* __restrict__ Y, const float* __restrict__ Z,
    float* __restrict__ H)
{
    int node = blockIdx.x * 8 + (threadIdx.x >> 5);
    if (node >= NN) return;
    int lane = threadIdx.x & 31;
    int beg = offs[node], end = offs[node + 1];

    float4 acc = {0.0f, 0.0f, 0.0f, 0.0f};
    const float4* Y4 = (const float4*)Y;

    for (int j = beg; j < end; j += 32) {
        int chunk = min(32, end - j);
        int id = (lane < chunk) ? csr[j + lane] : 0;
        int t = 0;
        for (; t + 4 <= chunk; t += 4) {
            int s0 = __shfl_sync(0xffffffffu, id, t);
            int s1 = __shfl_sync(0xffffffffu, id, t + 1);
            int s2 = __shfl_sync(0xffffffffu, id, t + 2);
            int s3 = __shfl_sync(0xffffffffu, id, t + 3);
            float4 v0 = __ldg(Y4 + s0 * 32 + lane);
            float4 v1 = __ldg(Y4 + s1 * 32 + lane);
            float4 v2 = __ldg(Y4 + s2 * 32 + lane);
            float4 v3 = __ldg(Y4 + s3 * 32 + lane);
            acc.x += v0.x + v1.x + v2.x + v3.x;
            acc.y += v0.y + v1.y + v2.y + v3.y;
            acc.z += v0.z + v1.z + v2.z + v3.z;
            acc.w += v0.w + v1.w + v2.w + v3.w;
        }
        for (; t < chunk; t++) {
            int s = __shfl_sync(0xffffffffu, id, t);
            float4 v = __ldg(Y4 + s * 32 + lane);
            acc.x += v.x; acc.y += v.y; acc.z += v.z; acc.w += v.w;
        }
    }

    float iv = 1.0f / (float)max(end - beg, 1);
    float4 z = __ldg((const float4*)Z + node * 32 + lane);
    float4 v;
    v.x = fmaxf(fmaf(acc.x, iv, z.x), 0.0f);
    v.y = fmaxf(fmaf(acc.y, iv, z.y), 0.0f);
    v.z = fmaxf(fmaf(acc.z, iv, z.z), 0.0f);
    v.w = fmaxf(fmaf(acc.w, iv, z.w), 0.0f);
    ((float4*)H)[node * 32 + lane] = v;
}

// ========== gather d=8 + finalize + log_softmax ==========
__global__ __launch_bounds__(256) void gather8(
    const int* __restrict__ csr, const int* __restrict__ offs,
    const float* __restrict__ Y, const float* __restrict__ Z,
    float* __restrict__ outh, float* __restrict__ outls)
{
    int node = blockIdx.x * 64 + (threadIdx.x >> 2);
    if (node >= NN) return;
    int lane4 = threadIdx.x & 3;
    int beg = offs[node], end = offs[node + 1];

    float a[8] = {0, 0, 0, 0, 0, 0, 0, 0};
    const float4* Y4 = (const float4*)Y;
    for (int j = beg + lane4; j < end; j += 4) {
        int s = csr[j];
        float4 v0 = __ldg(Y4 + s * 2);
        float4 v1 = __ldg(Y4 + s * 2 + 1);
        a[0] += v0.x; a[1] += v0.y; a[2] += v0.z; a[3] += v0.w;
        a[4] += v1.x; a[5] += v1.y; a[6] += v1.z; a[7] += v1.w;
    }
    #pragma unroll
    for (int i = 0; i < 8; i++) {
        a[i] += __shfl_xor_sync(0xffffffffu, a[i], 1);
        a[i] += __shfl_xor_sync(0xffffffffu, a[i], 2);
    }
    if (lane4 != 0) return;

    float iv = 1.0f / (float)max(end - beg, 1);
    float4 z0 = __ldg((const float4*)Z + node * 2);
    float4 z1 = __ldg((const float4*)Z + node * 2 + 1);
    float h[8];
    h[0] = fmaf(a[0], iv, z0.x); h[1] = fmaf(a[1], iv, z0.y);
    h[2] = fmaf(a[2], iv, z0.z); h[3] = fmaf(a[3], iv, z0.w);
    h[4] = fmaf(a[4], iv, z1.x); h[5] = fmaf(a[5], iv, z1.y);
    h[6] = fmaf(a[6], iv, z1.z); h[7] = fmaf(a[7], iv, z1.w);

    ((float4*)outh)[node * 2]     = make_float4(h[0], h[1], h[2], h[3]);
    ((float4*)outh)[node * 2 + 1] = make_float4(h[4], h[5], h[6], h[7]);

    if (outls) {
        float m = h[0];
        #pragma unroll
        for (int j = 1; j < 8; j++) m = fmaxf(m, h[j]);
        float sum = 0.0f;
        #pragma unroll
        for (int j = 0; j < 8; j++) sum += expf(h[j] - m);
        float lse = logf(sum) + m;
        ((float4*)outls)[node * 2]     = make_float4(h[0]-lse, h[1]-lse, h[2]-lse, h[3]-lse);
        ((float4*)outls)[node * 2 + 1] = make_float4(h[4]-lse, h[5]-lse, h[6]-lse, h[7]-lse);
    }
}

// ---------------- launch ----------------
extern "C" void kernel_launch(void* const* d_in, const int* in_sizes, int n_in,
                              void* d_out, int out_size)
{
    const float* x   = (const float*)d_in[0];
    const int*   ei  = (const int*)d_in[1];   // int32 (JAX default downcasts int64)
    const float* Wl0 = (const float*)d_in[2];
    const float* bl0 = (const float*)d_in[3];
    const float* Wr0 = (const float*)d_in[4];
    const float* Wl1 = (const float*)d_in[5];
    const float* bl1 = (const float*)d_in[6];
    const float* Wr1 = (const float*)d_in[7];
    const float* Wl2 = (const float*)d_in[8];
    const float* bl2 = (const float*)d_in[9];
    const float* Wr2 = (const float*)d_in[10];
    int E = in_sizes[1] / 2;
    if (E > EMAX) E = EMAX;
    float* out = (float*)d_out;

    void *py, *pz, *ph1, *ph2, *py2, *pz2, *pcnt, *poffs, *pcur, *pbsum, *pcsr;
    cudaGetSymbolAddress(&py,   g_y);
    cudaGetSymbolAddress(&pz,   g_z);
    cudaGetSymbolAddress(&ph1,  g_h1);
    cudaGetSymbolAddress(&ph2,  g_h2);
    cudaGetSymbolAddress(&py2,  g_y2);
    cudaGetSymbolAddress(&pz2,  g_z2);
    cudaGetSymbolAddress(&pcnt, g_cnt);
    cudaGetSymbolAddress(&poffs,g_offs);
    cudaGetSymbolAddress(&pcur, g_cursor);
    cudaGetSymbolAddress(&pbsum,g_bsum);
    cudaGetSymbolAddress(&pcsr, g_csr);

    cudaFuncSetAttribute(gemm_dual_mma, cudaFuncAttributeMaxDynamicSharedMemorySize, MMA_SMEM_BYTES);

    const int tiles = (NN + 63) / 64;

    // ---- build CSR (dst-major) ----
    cudaMemsetAsync(pcnt, 0, NN * sizeof(int));
    hist_kernel<<<(E + 255) / 256, 256>>>(ei, E, (int*)pcnt);
    scan_block<<<SCAN_NB, SCAN_BS>>>((const int*)pcnt, (int*)poffs, (int*)pbsum);
    scan_top<<<1, 256>>>((int*)pbsum);
    scan_add<<<(NN + 255) / 256, 256>>>((int*)poffs, (const int*)pbsum, (int*)pcur, E);
    fill_kernel<<<(E + 255) / 256, 256>>>(ei, E, (int*)pcur, (int*)pcsr);

    // ---- layer 0: x -> h1 ----
    gemm_dual_mma<<<tiles, 256, MMA_SMEM_BYTES>>>(x, Wl0, Wr0, bl0, (float*)py, (float*)pz, NN);
    gather128<<<(NN + 7) / 8, 256>>>((const int*)pcsr, (const int*)poffs,
                                     (const float*)py, (const float*)pz, (float*)ph1);

    // ---- layer 1: h1 -> h2 ----
    gemm_dual_mma<<<tiles, 256, MMA_SMEM_BYTES>>>((const float*)ph1, Wl1, Wr1, bl1,
                                                  (float*)py, (float*)pz, NN);
    gather128<<<(NN + 7) / 8, 256>>>((const int*)pcsr, (const int*)poffs,
                                     (const float*)py, (const float*)pz, (float*)ph2);

    // ---- layer 2: h2 -> out ----
    gemm_small<<<(NN + 15) / 16, 256>>>((const float*)ph2, Wl2, Wr2, bl2,
                                        (float*)py2, (float*)pz2);
    float* outls = (out_size >= 2 * NN * DOUT) ? (out + (size_t)NN * DOUT) : nullptr;
    gather8<<<(NN + 63) / 64, 256>>>((const int*)pcsr, (const int*)poffs,
                                     (const float*)py2, (const float*)pz2, out, outls);
}